// round 12
// baseline (speedup 1.0000x reference)
#include <cuda_runtime.h>
#include <math.h>

#define NN 100000
#define EE 1600000
#define BB 64
#define DIN 9
#define HD 128
#define KK 256
#define SLOTS 96
#define LN_EPS 1e-5f

// ---------------- scratch (zero at module load; cleanup restores zero each call) ----------------
__device__ float g_h0[NN * HD];
__device__ float g_h1[NN * HD];
__device__ float g_agg[NN * HD];
__device__ float g_wT[3 * KK * HD];   // per layer: [k][c]; k<128 = Wl^T, k>=128 = Wr^T
__device__ int   g_deg[NN];
__device__ int   g_slots[NN * SLOTS];
__device__ float g_psum[BB * HD];
__device__ unsigned g_pmax[BB * HD];
__device__ int   g_pcnt[BB];

// ---------------- launch 1: bucket build + weight transpose (fused) ----------------
__global__ void build_kernel(const int* __restrict__ src, const int* __restrict__ dst,
                             const float* __restrict__ Wl1, const float* __restrict__ Wr1,
                             const float* __restrict__ Wl2, const float* __restrict__ Wr2,
                             const float* __restrict__ Wl3, const float* __restrict__ Wr3) {
    int e = blockIdx.x * blockDim.x + threadIdx.x;
    if (e < 3 * KK * HD) {
        int c = e & 127;
        int k = (e >> 7) & 255;
        int L = e >> 15;
        const float* W;
        int kk = k;
        if (k < HD) {
            W = (L == 0) ? Wl1 : (L == 1) ? Wl2 : Wl3;
        } else {
            W = (L == 0) ? Wr1 : (L == 1) ? Wr2 : Wr3;
            kk = k - HD;
        }
        g_wT[e] = W[c * HD + kk];
    }
    if (e < EE) {
        int d = dst[e];
        int pos = atomicAdd(&g_deg[d], 1);
        if (pos < SLOTS) g_slots[d * SLOTS + pos] = src[e];
    }
}

// ---------------- launch 2: node embedder Linear(9->128) + LN + ReLU ----------------
#define ROWS_E 16
__global__ void embed_kernel(const float* __restrict__ x,
                             const float* __restrict__ W0,
                             const float* __restrict__ b0,
                             const float* __restrict__ g0,
                             const float* __restrict__ be0,
                             float* __restrict__ hout) {
    __shared__ float sx[DIN];
    __shared__ float red[8];
    int tid = threadIdx.x;
    float gc = g0[tid], bec = be0[tid], bc = b0[tid];
    float w[DIN];
#pragma unroll
    for (int k = 0; k < DIN; k++) w[k] = W0[tid * DIN + k];

    int row0 = blockIdx.x * ROWS_E;
    for (int r = 0; r < ROWS_E; r++) {
        int row = row0 + r;
        if (tid < DIN) sx[tid] = x[row * DIN + tid];
        __syncthreads();
        float acc = bc;
#pragma unroll
        for (int k = 0; k < DIN; k++) acc += w[k] * sx[k];
        float s1 = acc, s2 = acc * acc;
#pragma unroll
        for (int o = 16; o; o >>= 1) {
            s1 += __shfl_xor_sync(0xffffffffu, s1, o);
            s2 += __shfl_xor_sync(0xffffffffu, s2, o);
        }
        int wi = tid >> 5, l = tid & 31;
        if (l == 0) { red[wi] = s1; red[wi + 4] = s2; }
        __syncthreads();
        float t1 = red[0] + red[1] + red[2] + red[3];
        float t2 = red[4] + red[5] + red[6] + red[7];
        float mean = t1 * (1.0f / HD);
        float var = t2 * (1.0f / HD) - mean * mean;
        float rs = rsqrtf(var + LN_EPS);
        float v = (acc - mean) * rs * gc + bec;
        hout[row * HD + tid] = fmaxf(v, 0.0f);
        __syncthreads();
    }
}

// ---------------- mean aggregation v5: warp per node, cp.async staged gathers ----------------
// cp.async.cg has NO destination register -> ptxas cannot serialize the gathers
// to save registers (the R3-R11 hidden failure mode). MLP=8 per batch guaranteed
// by hardware. Each warp stages 8 x 512B neighbor rows into its private smem
// region, waits once, then sums via conflict-free LDS.128 (each lane reads only
// the 16B it copied itself -> no syncwarp needed).
__global__ void aggregate_kernel(const float* __restrict__ hin) {
    __shared__ __align__(16) char sbuf[8][8][512];   // 32KB: warp x slot x 512B
    int tid = threadIdx.x;
    int wi = tid >> 5;
    int lane = tid & 31;
    int node = (blockIdx.x * blockDim.x + tid) >> 5;
    if (node >= NN) return;

    int deg = g_deg[node];
    int n = min(deg, SLOTS);
    const int* sl = g_slots + node * SLOTS;
    float4 a = make_float4(0.f, 0.f, 0.f, 0.f);
    unsigned sbase = (unsigned)__cvta_generic_to_shared(&sbuf[wi][0][0]) + lane * 16;

    for (int j = 0; j < n; j += 8) {
        int m = min(n - j, 8);
#pragma unroll
        for (int t = 0; t < 8; t++) {
            if (t < m) {
                int idx = __ldg(&sl[j + t]);
                const float* gp = hin + (size_t)idx * HD + lane * 4;
                asm volatile("cp.async.cg.shared.global [%0], [%1], 16;\n"
                             :: "r"(sbase + t * 512), "l"(gp));
            }
        }
        asm volatile("cp.async.commit_group;\n" ::: "memory");
        asm volatile("cp.async.wait_group 0;\n" ::: "memory");
#pragma unroll
        for (int t = 0; t < 8; t++) {
            if (t < m) {
                float4 v = *(const float4*)(&sbuf[wi][t][lane * 16]);
                a.x += v.x; a.y += v.y; a.z += v.z; a.w += v.w;
            }
        }
    }
    float inv = 1.0f / (float)max(deg, 1);
    a.x *= inv; a.y *= inv; a.z *= inv; a.w *= inv;
    *reinterpret_cast<float4*>(g_agg + (size_t)node * HD + lane * 4) = a;
}

// ---------------- SAGE v3: 64x128xK=256 register-tiled GEMM + fused LN/ReLU ----------------
#define SBK 64
#define SROWS 64
#define SAGE3_SMEM (SBK * HD * 4 + SROWS * SBK * 4)   // 49152

__global__ __launch_bounds__(256, 3)
void sage3_kernel(const float* __restrict__ hin,
                  const float* __restrict__ wT,
                  const float* __restrict__ bl,
                  const float* __restrict__ gg,
                  const float* __restrict__ be,
                  float* __restrict__ hout) {
    extern __shared__ float sm[];
    float* w_s = sm;                 // [64][128]
    float* x_s = sm + SBK * HD;      // [64][64]

    int tid = threadIdx.x;
    int tx = tid & 31;
    int wy = tid >> 5;
    int row0 = blockIdx.x * SROWS;

    float acc[8][4];
#pragma unroll
    for (int r = 0; r < 8; r++) {
        acc[r][0] = 0.f; acc[r][1] = 0.f; acc[r][2] = 0.f; acc[r][3] = 0.f;
    }

    for (int ch = 0; ch < 4; ch++) {
        const float* xsrc = (ch < 2) ? g_agg : hin;
        int kofs = (ch & 1) * SBK;
        {
            int k4 = tid & 15, rr = tid >> 4;
#pragma unroll
            for (int it = 0; it < 4; it++) {
                int row = rr + it * 16;
                int grow = row0 + row;
                float4 v = make_float4(0.f, 0.f, 0.f, 0.f);
                if (grow < NN)
                    v = *(const float4*)(xsrc + (size_t)grow * HD + kofs + k4 * 4);
                ((float4*)(x_s + row * SBK))[k4] = v;
            }
        }
        {
            int c4 = tid & 31, kk = tid >> 5;
#pragma unroll
            for (int it = 0; it < 8; it++) {
                int k = kk + it * 8;
                ((float4*)(w_s + k * HD))[c4] =
                    *(const float4*)(wT + (size_t)(ch * SBK + k) * HD + c4 * 4);
            }
        }
        __syncthreads();

#pragma unroll 4
        for (int k4i = 0; k4i < SBK / 4; k4i++) {
            float4 b0 = ((float4*)(w_s + (4 * k4i + 0) * HD))[tx];
            float4 b1 = ((float4*)(w_s + (4 * k4i + 1) * HD))[tx];
            float4 b2 = ((float4*)(w_s + (4 * k4i + 2) * HD))[tx];
            float4 b3 = ((float4*)(w_s + (4 * k4i + 3) * HD))[tx];
#pragma unroll
            for (int r = 0; r < 8; r++) {
                float4 a = ((float4*)(x_s + (wy * 8 + r) * SBK))[k4i];  // broadcast
                acc[r][0] += a.x * b0.x + a.y * b1.x + a.z * b2.x + a.w * b3.x;
                acc[r][1] += a.x * b0.y + a.y * b1.y + a.z * b2.y + a.w * b3.y;
                acc[r][2] += a.x * b0.z + a.y * b1.z + a.z * b2.z + a.w * b3.z;
                acc[r][3] += a.x * b0.w + a.y * b1.w + a.z * b2.w + a.w * b3.w;
            }
        }
        __syncthreads();
    }

    float4 blv = *(const float4*)(bl + tx * 4);
    float4 gv  = *(const float4*)(gg + tx * 4);
    float4 bev = *(const float4*)(be + tx * 4);
#pragma unroll
    for (int r = 0; r < 8; r++) {
        float a0 = acc[r][0] + blv.x;
        float a1 = acc[r][1] + blv.y;
        float a2 = acc[r][2] + blv.z;
        float a3 = acc[r][3] + blv.w;
        float s1 = (a0 + a1) + (a2 + a3);
        float s2 = (a0 * a0 + a1 * a1) + (a2 * a2 + a3 * a3);
#pragma unroll
        for (int o = 16; o; o >>= 1) {
            s1 += __shfl_xor_sync(0xffffffffu, s1, o);
            s2 += __shfl_xor_sync(0xffffffffu, s2, o);
        }
        float mean = s1 * (1.0f / HD);
        float var  = s2 * (1.0f / HD) - mean * mean;
        float rs   = rsqrtf(var + LN_EPS);
        int row = row0 + wy * 8 + r;
        if (row < NN) {
            float4 o4;
            o4.x = fmaxf((a0 - mean) * rs * gv.x + bev.x, 0.f);
            o4.y = fmaxf((a1 - mean) * rs * gv.y + bev.y, 0.f);
            o4.z = fmaxf((a2 - mean) * rs * gv.z + bev.z, 0.f);
            o4.w = fmaxf((a3 - mean) * rs * gv.w + bev.w, 0.f);
            *(float4*)(hout + (size_t)row * HD + tx * 4) = o4;
        }
    }
}

// ---------------- pooling ----------------
#define POOL_CHUNK 256
__global__ void pool_kernel(const float* __restrict__ node,
                            const int* __restrict__ batch) {
    int n0 = blockIdx.x * POOL_CHUNK;
    int n1 = min(n0 + POOL_CHUNK, NN);
    int c = threadIdx.x;
    int cur = __ldg(&batch[n0]);
    float s = 0.0f, m = 0.0f;
    int cnt = 0;
    for (int i = n0; i < n1; i++) {
        int b = __ldg(&batch[i]);
        if (b != cur) {
            atomicAdd(&g_psum[cur * HD + c], s);
            atomicMax(&g_pmax[cur * HD + c], __float_as_uint(m));
            if (c == 0) atomicAdd(&g_pcnt[cur], cnt);
            cur = b; s = 0.0f; m = 0.0f; cnt = 0;
        }
        float v = node[(size_t)i * HD + c];
        s += v;
        m = fmaxf(m, v);
        cnt++;
    }
    atomicAdd(&g_psum[cur * HD + c], s);
    atomicMax(&g_pmax[cur * HD + c], __float_as_uint(m));
    if (c == 0) atomicAdd(&g_pcnt[cur], cnt);
}

__global__ void finalize_kernel(float* __restrict__ out) {
    int i = blockIdx.x * blockDim.x + threadIdx.x;
    if (i >= BB * HD) return;
    int b = i >> 7;
    int c = i & (HD - 1);
    float cnt = fmaxf((float)g_pcnt[b], 1.0f);
    out[(size_t)NN * HD + b * (2 * HD) + c] = g_psum[i] / cnt;
    out[(size_t)NN * HD + b * (2 * HD) + HD + c] = __uint_as_float(g_pmax[i]);
}

// ---------------- cleanup: restore zero state for next call (graph-replay safe) ----------------
__global__ void cleanup_kernel() {
    int i = blockIdx.x * blockDim.x + threadIdx.x;
    if (i < NN) g_deg[i] = 0;
    if (i < BB * HD) { g_psum[i] = 0.0f; g_pmax[i] = 0u; }
    if (i < BB) g_pcnt[i] = 0;
}

// ---------------- launch ----------------
extern "C" void kernel_launch(void* const* d_in, const int* in_sizes, int n_in,
                              void* d_out, int out_size) {
    const float* x   = (const float*)d_in[0];
    const int* eidx  = (const int*)d_in[1];
    const int* batch = (const int*)d_in[2];
    const float* W0 = (const float*)d_in[3];
    const float* b0 = (const float*)d_in[4];
    const float* g0 = (const float*)d_in[5];
    const float* be0 = (const float*)d_in[6];
    const float* Wl1 = (const float*)d_in[7];
    const float* bl1 = (const float*)d_in[8];
    const float* Wr1 = (const float*)d_in[9];
    const float* g1 = (const float*)d_in[10];
    const float* be1 = (const float*)d_in[11];
    const float* Wl2 = (const float*)d_in[12];
    const float* bl2 = (const float*)d_in[13];
    const float* Wr2 = (const float*)d_in[14];
    const float* g2 = (const float*)d_in[15];
    const float* be2 = (const float*)d_in[16];
    const float* Wl3 = (const float*)d_in[17];
    const float* bl3 = (const float*)d_in[18];
    const float* Wr3 = (const float*)d_in[19];
    const float* g3 = (const float*)d_in[20];
    const float* be3 = (const float*)d_in[21];
    float* out = (float*)d_out;

    const int* src = eidx;       // edge_index[0]
    const int* dst = eidx + EE;  // edge_index[1]

    static int attr_set = 0;
    if (!attr_set) {
        cudaFuncSetAttribute(sage3_kernel,
                             cudaFuncAttributeMaxDynamicSharedMemorySize, SAGE3_SMEM);
        attr_set = 1;
    }

    float* wT = 0;
    cudaGetSymbolAddress((void**)&wT, g_wT);

    int agg_blocks = (NN * 32 + 255) / 256;
    int sage_blocks = (NN + SROWS - 1) / SROWS;

    // 1: bucket build + weight transpose (state is zero at entry)
    build_kernel<<<(EE + 255) / 256, 256>>>(src, dst, Wl1, Wr1, Wl2, Wr2, Wl3, Wr3);
    // 2: embed
    embed_kernel<<<NN / ROWS_E, HD>>>(x, W0, b0, g0, be0, g_h0);
    // 3-7: aggregate layer 1 x5 (4 redundant, idempotent) -- ablation probe:
    //   delta vs single launch measures true per-aggregate cost, and one replica
    //   lands in the ncu capture slot with real state.
    aggregate_kernel<<<agg_blocks, 256>>>(g_h0);
    aggregate_kernel<<<agg_blocks, 256>>>(g_h0);
    aggregate_kernel<<<agg_blocks, 256>>>(g_h0);
    aggregate_kernel<<<agg_blocks, 256>>>(g_h0);
    aggregate_kernel<<<agg_blocks, 256>>>(g_h0);
    sage3_kernel<<<sage_blocks, 256, SAGE3_SMEM>>>(g_h0, wT + 0 * KK * HD, bl1, g1, be1, g_h1);
    // layer 2
    aggregate_kernel<<<agg_blocks, 256>>>(g_h1);
    sage3_kernel<<<sage_blocks, 256, SAGE3_SMEM>>>(g_h1, wT + 1 * KK * HD, bl2, g2, be2, g_h0);
    // layer 3 -> out
    aggregate_kernel<<<agg_blocks, 256>>>(g_h0);
    sage3_kernel<<<sage_blocks, 256, SAGE3_SMEM>>>(g_h0, wT + 2 * KK * HD, bl3, g3, be3, out);

    // pooling
    pool_kernel<<<(NN + POOL_CHUNK - 1) / POOL_CHUNK, HD>>>(out, batch);
    finalize_kernel<<<(BB * HD + 255) / 256, 256>>>(out);

    // restore zero state for the next (graph-replayed) call
    cleanup_kernel<<<(NN + 255) / 256, 256>>>();
}

// round 14
// speedup vs baseline: 2.0023x; 2.0023x over previous
#include <cuda_runtime.h>
#include <cstdint>
#include <math.h>

#define NN 100000
#define EE 1600000
#define BB 64
#define DIN 9
#define HD 128
#define KK 256
#define SLOTS 96
#define LN_EPS 1e-5f

// ---------------- scratch (zero at module load; cleanup restores zero each call) ----------------
__device__ float g_h0[NN * HD];
__device__ float g_h1[NN * HD];
__device__ float g_agg[NN * HD];
__device__ float g_wT[3 * KK * HD];   // per layer: [k][c]; k<128 = Wl^T, k>=128 = Wr^T
__device__ int   g_deg[NN];
__device__ int   g_slots[NN * SLOTS];
__device__ float g_psum[BB * HD];
__device__ unsigned g_pmax[BB * HD];
__device__ int   g_pcnt[BB];

// ---------------- launch 1: bucket build + weight transpose (fused) ----------------
__global__ void build_kernel(const int* __restrict__ src, const int* __restrict__ dst,
                             const float* __restrict__ Wl1, const float* __restrict__ Wr1,
                             const float* __restrict__ Wl2, const float* __restrict__ Wr2,
                             const float* __restrict__ Wl3, const float* __restrict__ Wr3) {
    int e = blockIdx.x * blockDim.x + threadIdx.x;
    if (e < 3 * KK * HD) {
        int c = e & 127;
        int k = (e >> 7) & 255;
        int L = e >> 15;
        const float* W;
        int kk = k;
        if (k < HD) {
            W = (L == 0) ? Wl1 : (L == 1) ? Wl2 : Wl3;
        } else {
            W = (L == 0) ? Wr1 : (L == 1) ? Wr2 : Wr3;
            kk = k - HD;
        }
        g_wT[e] = W[c * HD + kk];
    }
    if (e < EE) {
        int d = dst[e];
        int pos = atomicAdd(&g_deg[d], 1);
        if (pos < SLOTS) g_slots[d * SLOTS + pos] = src[e];
    }
}

// ---------------- launch 2: node embedder Linear(9->128) + LN + ReLU ----------------
#define ROWS_E 16
__global__ void embed_kernel(const float* __restrict__ x,
                             const float* __restrict__ W0,
                             const float* __restrict__ b0,
                             const float* __restrict__ g0,
                             const float* __restrict__ be0,
                             float* __restrict__ hout) {
    __shared__ float sx[DIN];
    __shared__ float red[8];
    int tid = threadIdx.x;
    float gc = g0[tid], bec = be0[tid], bc = b0[tid];
    float w[DIN];
#pragma unroll
    for (int k = 0; k < DIN; k++) w[k] = W0[tid * DIN + k];

    int row0 = blockIdx.x * ROWS_E;
    for (int r = 0; r < ROWS_E; r++) {
        int row = row0 + r;
        if (tid < DIN) sx[tid] = x[row * DIN + tid];
        __syncthreads();
        float acc = bc;
#pragma unroll
        for (int k = 0; k < DIN; k++) acc += w[k] * sx[k];
        float s1 = acc, s2 = acc * acc;
#pragma unroll
        for (int o = 16; o; o >>= 1) {
            s1 += __shfl_xor_sync(0xffffffffu, s1, o);
            s2 += __shfl_xor_sync(0xffffffffu, s2, o);
        }
        int wi = tid >> 5, l = tid & 31;
        if (l == 0) { red[wi] = s1; red[wi + 4] = s2; }
        __syncthreads();
        float t1 = red[0] + red[1] + red[2] + red[3];
        float t2 = red[4] + red[5] + red[6] + red[7];
        float mean = t1 * (1.0f / HD);
        float var = t2 * (1.0f / HD) - mean * mean;
        float rs = rsqrtf(var + LN_EPS);
        float v = (acc - mean) * rs * gc + bec;
        hout[row * HD + tid] = fmaxf(v, 0.0f);
        __syncthreads();
    }
}

// ---------------- mean aggregation v6: warp per node, TMA bulk row gather ----------------
// cp.async.bulk (UBLKCP) is issued by one lane, fire-and-forget through the TMA
// engine (L2 -> SMEM, no registers, no L1tex wavefronts, no scoreboard entry the
// compiler can serialize). Up to 16 x 512B neighbor rows per batch land in this
// warp's private SMEM slab; one mbarrier complete_tx gates the accumulate.
__global__ void aggregate_kernel(const float* __restrict__ hin) {
    __shared__ __align__(16) char sbuf[4][16 * 512];   // 32KB: 4 warps x 16 rows x 512B
    __shared__ unsigned long long smbar[4];
    int tid = threadIdx.x;
    int wi = tid >> 5;
    int lane = tid & 31;
    int node = blockIdx.x * 4 + wi;
    if (node >= NN) return;

    unsigned mbar = (unsigned)__cvta_generic_to_shared(&smbar[wi]);
    unsigned sb   = (unsigned)__cvta_generic_to_shared(&sbuf[wi][0]);
    if (lane == 0) {
        asm volatile("mbarrier.init.shared.b64 [%0], 1;" :: "r"(mbar) : "memory");
        asm volatile("fence.proxy.async.shared::cta;" ::: "memory");
    }
    __syncwarp();

    int deg = g_deg[node];
    int n = min(deg, SLOTS);
    const int* sl = g_slots + (size_t)node * SLOTS;
    float4 a = make_float4(0.f, 0.f, 0.f, 0.f);
    unsigned phase = 0;

    for (int j = 0; j < n; j += 16) {
        int m = min(n - j, 16);
        if (lane == 0) {
            asm volatile("mbarrier.arrive.expect_tx.shared.b64 _, [%0], %1;"
                         :: "r"(mbar), "r"(m * 512) : "memory");
            for (int t = 0; t < m; t++) {
                int idx = __ldg(&sl[j + t]);
                const float* gp = hin + (size_t)idx * HD;
                asm volatile(
                    "cp.async.bulk.shared::cta.global.mbarrier::complete_tx::bytes [%0], [%1], 512, [%2];"
                    :: "r"(sb + t * 512), "l"(gp), "r"(mbar) : "memory");
            }
        }
        // all lanes wait for batch completion (parity)
        {
            unsigned done;
            asm volatile(
                "{\n\t.reg .pred p;\n\t"
                "mbarrier.try_wait.parity.acquire.cta.shared::cta.b64 p, [%1], %2;\n\t"
                "selp.b32 %0, 1, 0, p;\n\t}"
                : "=r"(done) : "r"(mbar), "r"(phase) : "memory");
            while (!done) {
                asm volatile(
                    "{\n\t.reg .pred p;\n\t"
                    "mbarrier.try_wait.parity.acquire.cta.shared::cta.b64 p, [%1], %2, 0x989680;\n\t"
                    "selp.b32 %0, 1, 0, p;\n\t}"
                    : "=r"(done) : "r"(mbar), "r"(phase) : "memory");
            }
        }
        phase ^= 1;
#pragma unroll 4
        for (int t = 0; t < m; t++) {
            float4 v = *(const float4*)(&sbuf[wi][t * 512 + lane * 16]);
            a.x += v.x; a.y += v.y; a.z += v.z; a.w += v.w;
        }
        __syncwarp();   // all lanes done reading before next batch overwrites
    }

    float inv = 1.0f / (float)max(deg, 1);
    a.x *= inv; a.y *= inv; a.z *= inv; a.w *= inv;
    *reinterpret_cast<float4*>(g_agg + (size_t)node * HD + lane * 4) = a;
}

// ---------------- SAGE v3: 64x128xK=256 register-tiled GEMM + fused LN/ReLU ----------------
#define SBK 64
#define SROWS 64
#define SAGE3_SMEM (SBK * HD * 4 + SROWS * SBK * 4)   // 49152

__global__ __launch_bounds__(256, 3)
void sage3_kernel(const float* __restrict__ hin,
                  const float* __restrict__ wT,
                  const float* __restrict__ bl,
                  const float* __restrict__ gg,
                  const float* __restrict__ be,
                  float* __restrict__ hout) {
    extern __shared__ float sm[];
    float* w_s = sm;                 // [64][128]
    float* x_s = sm + SBK * HD;      // [64][64]

    int tid = threadIdx.x;
    int tx = tid & 31;
    int wy = tid >> 5;
    int row0 = blockIdx.x * SROWS;

    float acc[8][4];
#pragma unroll
    for (int r = 0; r < 8; r++) {
        acc[r][0] = 0.f; acc[r][1] = 0.f; acc[r][2] = 0.f; acc[r][3] = 0.f;
    }

    for (int ch = 0; ch < 4; ch++) {
        const float* xsrc = (ch < 2) ? g_agg : hin;
        int kofs = (ch & 1) * SBK;
        {
            int k4 = tid & 15, rr = tid >> 4;
#pragma unroll
            for (int it = 0; it < 4; it++) {
                int row = rr + it * 16;
                int grow = row0 + row;
                float4 v = make_float4(0.f, 0.f, 0.f, 0.f);
                if (grow < NN)
                    v = *(const float4*)(xsrc + (size_t)grow * HD + kofs + k4 * 4);
                ((float4*)(x_s + row * SBK))[k4] = v;
            }
        }
        {
            int c4 = tid & 31, kk = tid >> 5;
#pragma unroll
            for (int it = 0; it < 8; it++) {
                int k = kk + it * 8;
                ((float4*)(w_s + k * HD))[c4] =
                    *(const float4*)(wT + (size_t)(ch * SBK + k) * HD + c4 * 4);
            }
        }
        __syncthreads();

#pragma unroll 4
        for (int k4i = 0; k4i < SBK / 4; k4i++) {
            float4 b0 = ((float4*)(w_s + (4 * k4i + 0) * HD))[tx];
            float4 b1 = ((float4*)(w_s + (4 * k4i + 1) * HD))[tx];
            float4 b2 = ((float4*)(w_s + (4 * k4i + 2) * HD))[tx];
            float4 b3 = ((float4*)(w_s + (4 * k4i + 3) * HD))[tx];
#pragma unroll
            for (int r = 0; r < 8; r++) {
                float4 a = ((float4*)(x_s + (wy * 8 + r) * SBK))[k4i];  // broadcast
                acc[r][0] += a.x * b0.x + a.y * b1.x + a.z * b2.x + a.w * b3.x;
                acc[r][1] += a.x * b0.y + a.y * b1.y + a.z * b2.y + a.w * b3.y;
                acc[r][2] += a.x * b0.z + a.y * b1.z + a.z * b2.z + a.w * b3.z;
                acc[r][3] += a.x * b0.w + a.y * b1.w + a.z * b2.w + a.w * b3.w;
            }
        }
        __syncthreads();
    }

    float4 blv = *(const float4*)(bl + tx * 4);
    float4 gv  = *(const float4*)(gg + tx * 4);
    float4 bev = *(const float4*)(be + tx * 4);
#pragma unroll
    for (int r = 0; r < 8; r++) {
        float a0 = acc[r][0] + blv.x;
        float a1 = acc[r][1] + blv.y;
        float a2 = acc[r][2] + blv.z;
        float a3 = acc[r][3] + blv.w;
        float s1 = (a0 + a1) + (a2 + a3);
        float s2 = (a0 * a0 + a1 * a1) + (a2 * a2 + a3 * a3);
#pragma unroll
        for (int o = 16; o; o >>= 1) {
            s1 += __shfl_xor_sync(0xffffffffu, s1, o);
            s2 += __shfl_xor_sync(0xffffffffu, s2, o);
        }
        float mean = s1 * (1.0f / HD);
        float var  = s2 * (1.0f / HD) - mean * mean;
        float rs   = rsqrtf(var + LN_EPS);
        int row = row0 + wy * 8 + r;
        if (row < NN) {
            float4 o4;
            o4.x = fmaxf((a0 - mean) * rs * gv.x + bev.x, 0.f);
            o4.y = fmaxf((a1 - mean) * rs * gv.y + bev.y, 0.f);
            o4.z = fmaxf((a2 - mean) * rs * gv.z + bev.z, 0.f);
            o4.w = fmaxf((a3 - mean) * rs * gv.w + bev.w, 0.f);
            *(float4*)(hout + (size_t)row * HD + tx * 4) = o4;
        }
    }
}

// ---------------- pooling ----------------
#define POOL_CHUNK 256
__global__ void pool_kernel(const float* __restrict__ node,
                            const int* __restrict__ batch) {
    int n0 = blockIdx.x * POOL_CHUNK;
    int n1 = min(n0 + POOL_CHUNK, NN);
    int c = threadIdx.x;
    int cur = __ldg(&batch[n0]);
    float s = 0.0f, m = 0.0f;
    int cnt = 0;
    for (int i = n0; i < n1; i++) {
        int b = __ldg(&batch[i]);
        if (b != cur) {
            atomicAdd(&g_psum[cur * HD + c], s);
            atomicMax(&g_pmax[cur * HD + c], __float_as_uint(m));
            if (c == 0) atomicAdd(&g_pcnt[cur], cnt);
            cur = b; s = 0.0f; m = 0.0f; cnt = 0;
        }
        float v = node[(size_t)i * HD + c];
        s += v;
        m = fmaxf(m, v);
        cnt++;
    }
    atomicAdd(&g_psum[cur * HD + c], s);
    atomicMax(&g_pmax[cur * HD + c], __float_as_uint(m));
    if (c == 0) atomicAdd(&g_pcnt[cur], cnt);
}

__global__ void finalize_kernel(float* __restrict__ out) {
    int i = blockIdx.x * blockDim.x + threadIdx.x;
    if (i >= BB * HD) return;
    int b = i >> 7;
    int c = i & (HD - 1);
    float cnt = fmaxf((float)g_pcnt[b], 1.0f);
    out[(size_t)NN * HD + b * (2 * HD) + c] = g_psum[i] / cnt;
    out[(size_t)NN * HD + b * (2 * HD) + HD + c] = __uint_as_float(g_pmax[i]);
}

// ---------------- cleanup: restore zero state for next call (graph-replay safe) ----------------
__global__ void cleanup_kernel() {
    int i = blockIdx.x * blockDim.x + threadIdx.x;
    if (i < NN) g_deg[i] = 0;
    if (i < BB * HD) { g_psum[i] = 0.0f; g_pmax[i] = 0u; }
    if (i < BB) g_pcnt[i] = 0;
}

// ---------------- launch ----------------
extern "C" void kernel_launch(void* const* d_in, const int* in_sizes, int n_in,
                              void* d_out, int out_size) {
    const float* x   = (const float*)d_in[0];
    const int* eidx  = (const int*)d_in[1];
    const int* batch = (const int*)d_in[2];
    const float* W0 = (const float*)d_in[3];
    const float* b0 = (const float*)d_in[4];
    const float* g0 = (const float*)d_in[5];
    const float* be0 = (const float*)d_in[6];
    const float* Wl1 = (const float*)d_in[7];
    const float* bl1 = (const float*)d_in[8];
    const float* Wr1 = (const float*)d_in[9];
    const float* g1 = (const float*)d_in[10];
    const float* be1 = (const float*)d_in[11];
    const float* Wl2 = (const float*)d_in[12];
    const float* bl2 = (const float*)d_in[13];
    const float* Wr2 = (const float*)d_in[14];
    const float* g2 = (const float*)d_in[15];
    const float* be2 = (const float*)d_in[16];
    const float* Wl3 = (const float*)d_in[17];
    const float* bl3 = (const float*)d_in[18];
    const float* Wr3 = (const float*)d_in[19];
    const float* g3 = (const float*)d_in[20];
    const float* be3 = (const float*)d_in[21];
    float* out = (float*)d_out;

    const int* src = eidx;       // edge_index[0]
    const int* dst = eidx + EE;  // edge_index[1]

    static int attr_set = 0;
    if (!attr_set) {
        cudaFuncSetAttribute(sage3_kernel,
                             cudaFuncAttributeMaxDynamicSharedMemorySize, SAGE3_SMEM);
        attr_set = 1;
    }

    float* wT = 0;
    cudaGetSymbolAddress((void**)&wT, g_wT);

    int agg_blocks = (NN + 3) / 4;   // 4 warps/block, warp per node
    int sage_blocks = (NN + SROWS - 1) / SROWS;

    // 1: bucket build + weight transpose (state is zero at entry)
    build_kernel<<<(EE + 255) / 256, 256>>>(src, dst, Wl1, Wr1, Wl2, Wr2, Wl3, Wr3);
    // 2: embed
    embed_kernel<<<NN / ROWS_E, HD>>>(x, W0, b0, g0, be0, g_h0);
    // 3: aggregate layer 1; 4: one redundant replica so ncu's #4 slot profiles it
    aggregate_kernel<<<agg_blocks, 128>>>(g_h0);
    aggregate_kernel<<<agg_blocks, 128>>>(g_h0);
    sage3_kernel<<<sage_blocks, 256, SAGE3_SMEM>>>(g_h0, wT + 0 * KK * HD, bl1, g1, be1, g_h1);
    // layer 2
    aggregate_kernel<<<agg_blocks, 128>>>(g_h1);
    sage3_kernel<<<sage_blocks, 256, SAGE3_SMEM>>>(g_h1, wT + 1 * KK * HD, bl2, g2, be2, g_h0);
    // layer 3 -> out
    aggregate_kernel<<<agg_blocks, 128>>>(g_h0);
    sage3_kernel<<<sage_blocks, 256, SAGE3_SMEM>>>(g_h0, wT + 2 * KK * HD, bl3, g3, be3, out);

    // pooling
    pool_kernel<<<(NN + POOL_CHUNK - 1) / POOL_CHUNK, HD>>>(out, batch);
    finalize_kernel<<<(BB * HD + 255) / 256, 256>>>(out);

    // restore zero state for the next (graph-replayed) call
    cleanup_kernel<<<(NN + 255) / 256, 256>>>();
}

// round 15
// speedup vs baseline: 16.0598x; 8.0207x over previous
#include <cuda_runtime.h>
#include <cstdint>
#include <math.h>

#define NN 100000
#define EE 1600000
#define BB 64
#define DIN 9
#define HD 128
#define KK 256
#define SLOTS 96
#define LN_EPS 1e-5f

// ---------------- scratch (zero at module load; cleanup restores zero each call) ----------------
__device__ float g_h0[NN * HD];
__device__ float g_h1[NN * HD];
__device__ float g_agg[NN * HD];
__device__ float g_wT[3 * KK * HD];   // per layer: [k][c]; k<128 = Wl^T, k>=128 = Wr^T
__device__ int   g_degS[NN];          // out-degree (by src) -> slot fill
__device__ int   g_degD[NN];          // in-degree (by dst) -> mean divisor
__device__ int   g_slots[NN * SLOTS]; // out-neighbor (dst) lists keyed by src
__device__ float g_psum[BB * HD];
__device__ unsigned g_pmax[BB * HD];
__device__ int   g_pcnt[BB];

// ---------------- launch 1: bucket build (by SRC) + dst degree + weight transpose ----------------
__global__ void build_kernel(const int* __restrict__ src, const int* __restrict__ dst,
                             const float* __restrict__ Wl1, const float* __restrict__ Wr1,
                             const float* __restrict__ Wl2, const float* __restrict__ Wr2,
                             const float* __restrict__ Wl3, const float* __restrict__ Wr3) {
    int e = blockIdx.x * blockDim.x + threadIdx.x;
    if (e < 3 * KK * HD) {
        int c = e & 127;
        int k = (e >> 7) & 255;
        int L = e >> 15;
        const float* W;
        int kk = k;
        if (k < HD) {
            W = (L == 0) ? Wl1 : (L == 1) ? Wl2 : Wl3;
        } else {
            W = (L == 0) ? Wr1 : (L == 1) ? Wr2 : Wr3;
            kk = k - HD;
        }
        g_wT[e] = W[c * HD + kk];
    }
    if (e < EE) {
        int s = src[e];
        int d = dst[e];
        int pos = atomicAdd(&g_degS[s], 1);
        if (pos < SLOTS) g_slots[s * SLOTS + pos] = d;
        atomicAdd(&g_degD[d], 1);
    }
}

// ---------------- launch 2: node embedder Linear(9->128) + LN + ReLU ----------------
#define ROWS_E 16
__global__ void embed_kernel(const float* __restrict__ x,
                             const float* __restrict__ W0,
                             const float* __restrict__ b0,
                             const float* __restrict__ g0,
                             const float* __restrict__ be0,
                             float* __restrict__ hout) {
    __shared__ float sx[DIN];
    __shared__ float red[8];
    int tid = threadIdx.x;
    float gc = g0[tid], bec = be0[tid], bc = b0[tid];
    float w[DIN];
#pragma unroll
    for (int k = 0; k < DIN; k++) w[k] = W0[tid * DIN + k];

    int row0 = blockIdx.x * ROWS_E;
    for (int r = 0; r < ROWS_E; r++) {
        int row = row0 + r;
        if (tid < DIN) sx[tid] = x[row * DIN + tid];
        __syncthreads();
        float acc = bc;
#pragma unroll
        for (int k = 0; k < DIN; k++) acc += w[k] * sx[k];
        float s1 = acc, s2 = acc * acc;
#pragma unroll
        for (int o = 16; o; o >>= 1) {
            s1 += __shfl_xor_sync(0xffffffffu, s1, o);
            s2 += __shfl_xor_sync(0xffffffffu, s2, o);
        }
        int wi = tid >> 5, l = tid & 31;
        if (l == 0) { red[wi] = s1; red[wi + 4] = s2; }
        __syncthreads();
        float t1 = red[0] + red[1] + red[2] + red[3];
        float t2 = red[4] + red[5] + red[6] + red[7];
        float mean = t1 * (1.0f / HD);
        float var = t2 * (1.0f / HD) - mean * mean;
        float rs = rsqrtf(var + LN_EPS);
        float v = (acc - mean) * rs * gc + bec;
        hout[row * HD + tid] = fmaxf(v, 0.0f);
        __syncthreads();
    }
}

// ---------------- zero g_agg before scatter accumulation ----------------
__global__ void zero_agg_kernel() {
    int i = blockIdx.x * blockDim.x + threadIdx.x;
    ((float4*)g_agg)[i] = make_float4(0.f, 0.f, 0.f, 0.f);   // NN*HD/4 threads
}

// ---------------- aggregation v7: SRC-parallel scatter with red.v4 (fire-and-forget) ----------------
// Warp per src node: ONE sequential 512B read of h[src] (no random loads at all),
// then one red.global.add.v4.f32 per out-neighbor. REDs have no return value ->
// no warp ever waits on a random address. Random traffic is now pure throughput
// on the LTS atomic ALU instead of a latency chain.
__global__ void scatter_kernel(const float* __restrict__ hin) {
    int node = (blockIdx.x * blockDim.x + threadIdx.x) >> 5;
    int lane = threadIdx.x & 31;
    if (node >= NN) return;
    int m = min(g_degS[node], SLOTS);
    if (m == 0) return;

    float4 v = *((const float4*)(hin + (size_t)node * HD) + lane);  // sequential, coalesced
    const int* sl = g_slots + (size_t)node * SLOTS;
    for (int j = 0; j < m; j++) {
        int d = sl[j];                         // broadcast load (L1-hit)
        float* dp = g_agg + (size_t)d * HD + lane * 4;
        asm volatile("red.global.add.v4.f32 [%0], {%1, %2, %3, %4};"
                     :: "l"(dp), "f"(v.x), "f"(v.y), "f"(v.z), "f"(v.w)
                     : "memory");
    }
}

// ---------------- SAGE v3: 64x128xK=256 register-tiled GEMM + fused mean + LN/ReLU ----------------
// g_agg holds SUMS; the mean-divide (1/degD) is folded into the x staging.
#define SBK 64
#define SROWS 64
#define SAGE3_SMEM (SBK * HD * 4 + SROWS * SBK * 4)   // 49152

__global__ __launch_bounds__(256, 3)
void sage3_kernel(const float* __restrict__ hin,
                  const float* __restrict__ wT,
                  const float* __restrict__ bl,
                  const float* __restrict__ gg,
                  const float* __restrict__ be,
                  float* __restrict__ hout) {
    extern __shared__ float sm[];
    float* w_s = sm;                 // [64][128]
    float* x_s = sm + SBK * HD;      // [64][64]

    int tid = threadIdx.x;
    int tx = tid & 31;
    int wy = tid >> 5;
    int row0 = blockIdx.x * SROWS;

    float acc[8][4];
#pragma unroll
    for (int r = 0; r < 8; r++) {
        acc[r][0] = 0.f; acc[r][1] = 0.f; acc[r][2] = 0.f; acc[r][3] = 0.f;
    }

    for (int ch = 0; ch < 4; ch++) {
        const float* xsrc = (ch < 2) ? g_agg : hin;
        int kofs = (ch & 1) * SBK;
        {
            int k4 = tid & 15, rr = tid >> 4;
#pragma unroll
            for (int it = 0; it < 4; it++) {
                int row = rr + it * 16;
                int grow = row0 + row;
                float4 v = make_float4(0.f, 0.f, 0.f, 0.f);
                if (grow < NN) {
                    v = *(const float4*)(xsrc + (size_t)grow * HD + kofs + k4 * 4);
                    if (ch < 2) {
                        float invd = 1.0f / fmaxf((float)__ldg(&g_degD[grow]), 1.0f);
                        v.x *= invd; v.y *= invd; v.z *= invd; v.w *= invd;
                    }
                }
                ((float4*)(x_s + row * SBK))[k4] = v;
            }
        }
        {
            int c4 = tid & 31, kk = tid >> 5;
#pragma unroll
            for (int it = 0; it < 8; it++) {
                int k = kk + it * 8;
                ((float4*)(w_s + k * HD))[c4] =
                    *(const float4*)(wT + (size_t)(ch * SBK + k) * HD + c4 * 4);
            }
        }
        __syncthreads();

#pragma unroll 4
        for (int k4i = 0; k4i < SBK / 4; k4i++) {
            float4 b0 = ((float4*)(w_s + (4 * k4i + 0) * HD))[tx];
            float4 b1 = ((float4*)(w_s + (4 * k4i + 1) * HD))[tx];
            float4 b2 = ((float4*)(w_s + (4 * k4i + 2) * HD))[tx];
            float4 b3 = ((float4*)(w_s + (4 * k4i + 3) * HD))[tx];
#pragma unroll
            for (int r = 0; r < 8; r++) {
                float4 a = ((float4*)(x_s + (wy * 8 + r) * SBK))[k4i];  // broadcast
                acc[r][0] += a.x * b0.x + a.y * b1.x + a.z * b2.x + a.w * b3.x;
                acc[r][1] += a.x * b0.y + a.y * b1.y + a.z * b2.y + a.w * b3.y;
                acc[r][2] += a.x * b0.z + a.y * b1.z + a.z * b2.z + a.w * b3.z;
                acc[r][3] += a.x * b0.w + a.y * b1.w + a.z * b2.w + a.w * b3.w;
            }
        }
        __syncthreads();
    }

    float4 blv = *(const float4*)(bl + tx * 4);
    float4 gv  = *(const float4*)(gg + tx * 4);
    float4 bev = *(const float4*)(be + tx * 4);
#pragma unroll
    for (int r = 0; r < 8; r++) {
        float a0 = acc[r][0] + blv.x;
        float a1 = acc[r][1] + blv.y;
        float a2 = acc[r][2] + blv.z;
        float a3 = acc[r][3] + blv.w;
        float s1 = (a0 + a1) + (a2 + a3);
        float s2 = (a0 * a0 + a1 * a1) + (a2 * a2 + a3 * a3);
#pragma unroll
        for (int o = 16; o; o >>= 1) {
            s1 += __shfl_xor_sync(0xffffffffu, s1, o);
            s2 += __shfl_xor_sync(0xffffffffu, s2, o);
        }
        float mean = s1 * (1.0f / HD);
        float var  = s2 * (1.0f / HD) - mean * mean;
        float rs   = rsqrtf(var + LN_EPS);
        int row = row0 + wy * 8 + r;
        if (row < NN) {
            float4 o4;
            o4.x = fmaxf((a0 - mean) * rs * gv.x + bev.x, 0.f);
            o4.y = fmaxf((a1 - mean) * rs * gv.y + bev.y, 0.f);
            o4.z = fmaxf((a2 - mean) * rs * gv.z + bev.z, 0.f);
            o4.w = fmaxf((a3 - mean) * rs * gv.w + bev.w, 0.f);
            *(float4*)(hout + (size_t)row * HD + tx * 4) = o4;
        }
    }
}

// ---------------- pooling ----------------
#define POOL_CHUNK 256
__global__ void pool_kernel(const float* __restrict__ node,
                            const int* __restrict__ batch) {
    int n0 = blockIdx.x * POOL_CHUNK;
    int n1 = min(n0 + POOL_CHUNK, NN);
    int c = threadIdx.x;
    int cur = __ldg(&batch[n0]);
    float s = 0.0f, m = 0.0f;
    int cnt = 0;
    for (int i = n0; i < n1; i++) {
        int b = __ldg(&batch[i]);
        if (b != cur) {
            atomicAdd(&g_psum[cur * HD + c], s);
            atomicMax(&g_pmax[cur * HD + c], __float_as_uint(m));
            if (c == 0) atomicAdd(&g_pcnt[cur], cnt);
            cur = b; s = 0.0f; m = 0.0f; cnt = 0;
        }
        float v = node[(size_t)i * HD + c];
        s += v;
        m = fmaxf(m, v);
        cnt++;
    }
    atomicAdd(&g_psum[cur * HD + c], s);
    atomicMax(&g_pmax[cur * HD + c], __float_as_uint(m));
    if (c == 0) atomicAdd(&g_pcnt[cur], cnt);
}

__global__ void finalize_kernel(float* __restrict__ out) {
    int i = blockIdx.x * blockDim.x + threadIdx.x;
    if (i >= BB * HD) return;
    int b = i >> 7;
    int c = i & (HD - 1);
    float cnt = fmaxf((float)g_pcnt[b], 1.0f);
    out[(size_t)NN * HD + b * (2 * HD) + c] = g_psum[i] / cnt;
    out[(size_t)NN * HD + b * (2 * HD) + HD + c] = __uint_as_float(g_pmax[i]);
}

// ---------------- cleanup: restore zero state for next call (graph-replay safe) ----------------
__global__ void cleanup_kernel() {
    int i = blockIdx.x * blockDim.x + threadIdx.x;
    if (i < NN) { g_degS[i] = 0; g_degD[i] = 0; }
    if (i < BB * HD) { g_psum[i] = 0.0f; g_pmax[i] = 0u; }
    if (i < BB) g_pcnt[i] = 0;
}

// ---------------- launch ----------------
extern "C" void kernel_launch(void* const* d_in, const int* in_sizes, int n_in,
                              void* d_out, int out_size) {
    const float* x   = (const float*)d_in[0];
    const int* eidx  = (const int*)d_in[1];
    const int* batch = (const int*)d_in[2];
    const float* W0 = (const float*)d_in[3];
    const float* b0 = (const float*)d_in[4];
    const float* g0 = (const float*)d_in[5];
    const float* be0 = (const float*)d_in[6];
    const float* Wl1 = (const float*)d_in[7];
    const float* bl1 = (const float*)d_in[8];
    const float* Wr1 = (const float*)d_in[9];
    const float* g1 = (const float*)d_in[10];
    const float* be1 = (const float*)d_in[11];
    const float* Wl2 = (const float*)d_in[12];
    const float* bl2 = (const float*)d_in[13];
    const float* Wr2 = (const float*)d_in[14];
    const float* g2 = (const float*)d_in[15];
    const float* be2 = (const float*)d_in[16];
    const float* Wl3 = (const float*)d_in[17];
    const float* bl3 = (const float*)d_in[18];
    const float* Wr3 = (const float*)d_in[19];
    const float* g3 = (const float*)d_in[20];
    const float* be3 = (const float*)d_in[21];
    float* out = (float*)d_out;

    const int* src = eidx;       // edge_index[0]
    const int* dst = eidx + EE;  // edge_index[1]

    static int attr_set = 0;
    if (!attr_set) {
        cudaFuncSetAttribute(sage3_kernel,
                             cudaFuncAttributeMaxDynamicSharedMemorySize, SAGE3_SMEM);
        attr_set = 1;
    }

    float* wT = 0;
    cudaGetSymbolAddress((void**)&wT, g_wT);

    int scat_blocks = (NN * 32 + 255) / 256;         // warp per src node
    int zero_blocks = (NN * HD / 4 + 255) / 256;
    int sage_blocks = (NN + SROWS - 1) / SROWS;

    // 1: build (by src) + weight transpose  (state zero at entry)
    build_kernel<<<(EE + 255) / 256, 256>>>(src, dst, Wl1, Wr1, Wl2, Wr2, Wl3, Wr3);
    // 2: embed
    embed_kernel<<<NN / ROWS_E, HD>>>(x, W0, b0, g0, be0, g_h0);
    // layer 1 (scatter at launch #4 = profiled slot)
    zero_agg_kernel<<<zero_blocks, 256>>>();
    scatter_kernel<<<scat_blocks, 256>>>(g_h0);
    sage3_kernel<<<sage_blocks, 256, SAGE3_SMEM>>>(g_h0, wT + 0 * KK * HD, bl1, g1, be1, g_h1);
    // layer 2
    zero_agg_kernel<<<zero_blocks, 256>>>();
    scatter_kernel<<<scat_blocks, 256>>>(g_h1);
    sage3_kernel<<<sage_blocks, 256, SAGE3_SMEM>>>(g_h1, wT + 1 * KK * HD, bl2, g2, be2, g_h0);
    // layer 3 -> out
    zero_agg_kernel<<<zero_blocks, 256>>>();
    scatter_kernel<<<scat_blocks, 256>>>(g_h0);
    sage3_kernel<<<sage_blocks, 256, SAGE3_SMEM>>>(g_h0, wT + 2 * KK * HD, bl3, g3, be3, out);

    // pooling
    pool_kernel<<<(NN + POOL_CHUNK - 1) / POOL_CHUNK, HD>>>(out, batch);
    finalize_kernel<<<(BB * HD + 255) / 256, 256>>>(out);

    // restore zero state for the next (graph-replayed) call
    cleanup_kernel<<<(NN + 255) / 256, 256>>>();
}